// round 10
// baseline (speedup 1.0000x reference)
#include <cuda_runtime.h>
#include <cuda_bf16.h>
#include <cuda_fp16.h>
#include <cuda_fp8.h>
#include <math.h>
#include <stdint.h>

#define S_DIM 4
#define B_DIM 4096
#define D_DIM 768
#define K_DIM 8192
#define N_ROWS 16384
#define RPC 16                  // rows per CTA in row passes
#define TOT_ELEMS 134217728LL   // N_ROWS * K_DIM

#define ROWB 3072               // bytes per packed row: 768 fp8 + 768 fp8 + 768 fp16

// ---------------- scratch (device globals; no allocation allowed) ----------------
__device__ float g_logits[(size_t)N_ROWS * K_DIM];   // 512 MB
__device__ float g_inv_norm[N_ROWS];
__device__ float g_shift[S_DIM * K_DIM];
__device__ float g_c[S_DIM * K_DIM];
__device__ float g_A[S_DIM * K_DIM];
__device__ float g_r[N_ROWS];
__device__ float g_lse[N_ROWS];
__device__ float g_part_m[4 * S_DIM * K_DIM];
__device__ float g_part_s[4 * S_DIM * K_DIM];
__device__ float g_loss;

// packed operand rows:  [ r_a*2^19 (e4m3, 768B) | a*2^7 (e4m3, 768B) | fp16(a) (1536B) ]
// B rows:               [ b (e4m3)              | r_b*2^12 (e4m3)    | fp16(b)         ]
__device__ uint8_t g_Acat[(size_t)N_ROWS * ROWB];   // 50.3 MB
__device__ uint8_t g_Bcat[(size_t)K_DIM * ROWB];    // 25.2 MB

// ---------------- helpers ---------------------------------------------------------
__device__ __forceinline__ uint32_t smem_u32(const void* p) {
    uint32_t a;
    asm("{ .reg .u64 t; cvta.to.shared.u64 t, %1; cvt.u32.u64 %0, t; }" : "=r"(a) : "l"(p));
    return a;
}

#define CP_ASYNC16(s, g) \
    asm volatile("cp.async.cg.shared.global [%0], [%1], 16;" :: "r"(s), "l"(g) : "memory")
#define CP_COMMIT() asm volatile("cp.async.commit_group;" ::: "memory")
#define CP_WAIT1()  asm volatile("cp.async.wait_group 1;" ::: "memory")

#define LDMATRIX_X4(r0, r1, r2, r3, addr) \
    asm volatile("ldmatrix.sync.aligned.m8n8.x4.shared.b16 {%0,%1,%2,%3}, [%4];" \
        : "=r"(r0), "=r"(r1), "=r"(r2), "=r"(r3) : "r"(addr))

#define MMA_16816_F16(c0, c1, c2, c3, a0, a1, a2, a3, b0, b1) \
    asm volatile("mma.sync.aligned.m16n8k16.row.col.f32.f16.f16.f32 " \
        "{%0,%1,%2,%3}, {%4,%5,%6,%7}, {%8,%9}, {%0,%1,%2,%3};" \
        : "+f"(c0), "+f"(c1), "+f"(c2), "+f"(c3) \
        : "r"(a0), "r"(a1), "r"(a2), "r"(a3), "r"(b0), "r"(b1))

#define MMA_16832_F8(c0, c1, c2, c3, a0, a1, a2, a3, b0, b1) \
    asm volatile("mma.sync.aligned.m16n8k32.row.col.f32.e4m3.e4m3.f32 " \
        "{%0,%1,%2,%3}, {%4,%5,%6,%7}, {%8,%9}, {%0,%1,%2,%3};" \
        : "+f"(c0), "+f"(c1), "+f"(c2), "+f"(c3) \
        : "r"(a0), "r"(a1), "r"(a2), "r"(a3), "r"(b0), "r"(b1))

// ---------------- fast exp on the FMA pipe (rel err ~1e-7 for x <= 50) ----------
__device__ __forceinline__ float fast_exp(float x) {
    float t = x * 1.4426950408889634f;
    t = fmaxf(t, -127.0f);
    float n = rintf(t);
    float f = t - n;
    float p = 1.5403530393381609e-4f;
    p = fmaf(p, f, 1.3333558146428443e-3f);
    p = fmaf(p, f, 9.6181291076284772e-3f);
    p = fmaf(p, f, 5.5504108664821580e-2f);
    p = fmaf(p, f, 2.4022650695910072e-1f);
    p = fmaf(p, f, 6.9314718055994531e-1f);
    p = fmaf(p, f, 1.0f);
    return __int_as_float(((int)n + 127) << 23) * p;
}

// ---------------- K0: row norms ---------------------------------------------------
__global__ void __launch_bounds__(256) norm_kernel(const float* __restrict__ X) {
    int row = blockIdx.x * 8 + (threadIdx.x >> 5);
    int lane = threadIdx.x & 31;
    const float* xr = X + (size_t)row * D_DIM;
    float ss = 0.f;
    for (int i = lane; i < D_DIM; i += 32) { float v = xr[i]; ss = fmaf(v, v, ss); }
    #pragma unroll
    for (int o = 16; o > 0; o >>= 1) ss += __shfl_xor_sync(0xffffffffu, ss, o);
    if (lane == 0) g_inv_norm[row] = 1.0f / fmaxf(sqrtf(ss), 1e-7f);
}

// ---------------- split converters ------------------------------------------------
__device__ __forceinline__ uint32_t pack4_e4m3(float x0, float x1, float x2, float x3) {
    uint32_t lo = __nv_cvt_float2_to_fp8x2(make_float2(x0, x1), __NV_SATFINITE, __NV_E4M3);
    uint32_t hi = __nv_cvt_float2_to_fp8x2(make_float2(x2, x3), __NV_SATFINITE, __NV_E4M3);
    return (lo & 0xffffu) | (hi << 16);
}

// one unit = (row, group of 8 cols); A: scale by inv_norm
__global__ void __launch_bounds__(256) convA_kernel(const float* __restrict__ X) {
    size_t u = (size_t)blockIdx.x * 256 + threadIdx.x;
    int row = (int)(u / 96);
    int c8 = (int)(u % 96) * 8;
    float sc = g_inv_norm[row];
    const float* xr = X + (size_t)row * D_DIM + c8;
    float a[8], r[8];
    __half hv[8];
    #pragma unroll
    for (int i = 0; i < 8; i++) {
        a[i] = xr[i] * sc;
        hv[i] = __float2half(a[i]);
        r[i] = a[i] - __half2float(hv[i]);
    }
    uint8_t* rowp = g_Acat + (size_t)row * ROWB;
    uint2 c1 = make_uint2(pack4_e4m3(r[0] * 524288.f, r[1] * 524288.f, r[2] * 524288.f, r[3] * 524288.f),
                          pack4_e4m3(r[4] * 524288.f, r[5] * 524288.f, r[6] * 524288.f, r[7] * 524288.f));
    uint2 c2 = make_uint2(pack4_e4m3(a[0] * 128.f, a[1] * 128.f, a[2] * 128.f, a[3] * 128.f),
                          pack4_e4m3(a[4] * 128.f, a[5] * 128.f, a[6] * 128.f, a[7] * 128.f));
    *(uint2*)(rowp + c8) = c1;
    *(uint2*)(rowp + 768 + c8) = c2;
    *(uint4*)(rowp + 1536 + 2 * c8) = *(uint4*)hv;
}

__global__ void __launch_bounds__(256) convB_kernel(const float* __restrict__ Wm) {
    size_t u = (size_t)blockIdx.x * 256 + threadIdx.x;
    int row = (int)(u / 96);
    int c8 = (int)(u % 96) * 8;
    const float* wr = Wm + (size_t)row * D_DIM + c8;
    float b[8], r[8];
    __half hv[8];
    #pragma unroll
    for (int i = 0; i < 8; i++) {
        b[i] = wr[i];
        hv[i] = __float2half(b[i]);
        r[i] = b[i] - __half2float(hv[i]);
    }
    uint8_t* rowp = g_Bcat + (size_t)row * ROWB;
    uint2 c1 = make_uint2(pack4_e4m3(b[0], b[1], b[2], b[3]),
                          pack4_e4m3(b[4], b[5], b[6], b[7]));
    uint2 c2 = make_uint2(pack4_e4m3(r[0] * 4096.f, r[1] * 4096.f, r[2] * 4096.f, r[3] * 4096.f),
                          pack4_e4m3(r[4] * 4096.f, r[5] * 4096.f, r[6] * 4096.f, r[7] * 4096.f));
    *(uint2*)(rowp + c8) = c1;
    *(uint2*)(rowp + 768 + c8) = c2;
    *(uint4*)(rowp + 1536 + 2 * c8) = *(uint4*)hv;
}

// ---------------- K1: mixed fp8/fp16 GEMM (fp32 accum) ---------------------------
// 128x128 CTA, 8 warps of 64x32, 2 CTA/SM, 128 B/row per iteration.
// iters 0..11: e4m3 correction planes (k32/MMA); iter 11 end: acc *= 2^-19;
// iters 12..23: fp16 main planes (k16/MMA).
#define BM 128
#define BN 128
#define NIT 24
#define NCORR 12
#define RSTR 144                    // 128B data + 16B pad ((9r+c)%8 permutation)
#define STAGE_HALF (128 * RSTR)     // 18432
#define STAGE_BYTES (2 * STAGE_HALF)
#define NSTAGE 3
#define GEMM_SMEM (NSTAGE * STAGE_BYTES)   // 110592 (2 CTA/SM)
#define CORR_SCALE 1.9073486328125e-06f    // 2^-19

__global__ void __launch_bounds__(256, 2) gemm_hmma(const uint8_t* __restrict__ A3,
                                                    const uint8_t* __restrict__ B3) {
    extern __shared__ char smem[];
    const uint32_t sbase = smem_u32(smem);
    const int tid = threadIdx.x;
    const int wid = tid >> 5, lid = tid & 31;
    const int bm = blockIdx.y * BM;
    const int bn = blockIdx.x * BN;
    const int wm = (wid & 1) * 64;      // 2 warps in m
    const int wn = (wid >> 1) * 32;     // 4 warps in n

    // cp.async: 1024 16B-chunks per matrix per stage, 4 per thread each.
    const uint8_t* gA[4];
    const uint8_t* gB[4];
    uint32_t so[4];
    #pragma unroll
    for (int i = 0; i < 4; i++) {
        const int ch = tid + i * 256;
        const int r = ch >> 3, c = ch & 7;
        gA[i] = A3 + (size_t)(bm + r) * ROWB + c * 16;
        gB[i] = B3 + (size_t)(bn + r) * ROWB + c * 16;
        so[i] = r * RSTR + c * 16;
    }

    const int lrow = (lid & 7) + ((lid >> 3) & 1) * 8;
    const int lkb = ((lid >> 4) & 1) * 16;
    const uint32_t aoff = (uint32_t)(wm + lrow) * RSTR + lkb;
    const uint32_t boff = (uint32_t)(wn + lrow) * RSTR + lkb;

    float acc[4][4][4];
    #pragma unroll
    for (int i = 0; i < 4; i++)
        #pragma unroll
        for (int j = 0; j < 4; j++)
            #pragma unroll
            for (int q = 0; q < 4; q++) acc[i][j][q] = 0.f;

    // prologue: stages 0,1
    #pragma unroll
    for (int st = 0; st < 2; st++) {
        const int k0 = st * 128;
        const uint32_t sa = sbase + st * STAGE_BYTES;
        const uint32_t sb = sa + STAGE_HALF;
        #pragma unroll
        for (int i = 0; i < 4; i++) {
            CP_ASYNC16(sa + so[i], gA[i] + k0);
            CP_ASYNC16(sb + so[i], gB[i] + k0);
        }
        CP_COMMIT();
    }

    int st = 0;
    for (int it = 0; it < NIT; it++) {
        CP_WAIT1();
        __syncthreads();

        if (it + 2 < NIT) {
            const int ps = (st + 2 >= NSTAGE) ? st + 2 - NSTAGE : st + 2;
            const int k0 = (it + 2) * 128;
            const uint32_t sa = sbase + ps * STAGE_BYTES;
            const uint32_t sb = sa + STAGE_HALF;
            #pragma unroll
            for (int i = 0; i < 4; i++) {
                CP_ASYNC16(sa + so[i], gA[i] + k0);
                CP_ASYNC16(sb + so[i], gB[i] + k0);
            }
        }
        CP_COMMIT();

        const uint32_t sa = sbase + st * STAGE_BYTES;
        const uint32_t sb = sa + STAGE_HALF;
        if (it < NCORR) {
            // -------- fp8 correction phase: 32B = one k32 MMA step --------
            #pragma unroll
            for (int ks = 0; ks < 4; ks++) {
                uint32_t a[4][4];
                #pragma unroll
                for (int mt = 0; mt < 4; mt++) {
                    uint32_t ad = sa + aoff + mt * (16 * RSTR) + ks * 32;
                    LDMATRIX_X4(a[mt][0], a[mt][1], a[mt][2], a[mt][3], ad);
                }
                uint32_t b[2][4];
                #pragma unroll
                for (int np = 0; np < 2; np++) {
                    uint32_t bd = sb + boff + np * (16 * RSTR) + ks * 32;
                    LDMATRIX_X4(b[np][0], b[np][1], b[np][2], b[np][3], bd);
                }
                #pragma unroll
                for (int mt = 0; mt < 4; mt++) {
                    #pragma unroll
                    for (int nt = 0; nt < 4; nt++) {
                        const int np = nt >> 1, no = nt & 1;
                        MMA_16832_F8(acc[mt][nt][0], acc[mt][nt][1], acc[mt][nt][2], acc[mt][nt][3],
                                     a[mt][0], a[mt][1], a[mt][2], a[mt][3],
                                     b[np][no], b[np][2 + no]);
                    }
                }
            }
            if (it == NCORR - 1) {
                #pragma unroll
                for (int i = 0; i < 4; i++)
                    #pragma unroll
                    for (int j = 0; j < 4; j++)
                        #pragma unroll
                        for (int q = 0; q < 4; q++) acc[i][j][q] *= CORR_SCALE;
            }
        } else {
            // -------- fp16 main phase: 32B = one k16 MMA step --------
            #pragma unroll
            for (int ks = 0; ks < 4; ks++) {
                uint32_t a[4][4];
                #pragma unroll
                for (int mt = 0; mt < 4; mt++) {
                    uint32_t ad = sa + aoff + mt * (16 * RSTR) + ks * 32;
                    LDMATRIX_X4(a[mt][0], a[mt][1], a[mt][2], a[mt][3], ad);
                }
                uint32_t b[2][4];
                #pragma unroll
                for (int np = 0; np < 2; np++) {
                    uint32_t bd = sb + boff + np * (16 * RSTR) + ks * 32;
                    LDMATRIX_X4(b[np][0], b[np][1], b[np][2], b[np][3], bd);
                }
                #pragma unroll
                for (int mt = 0; mt < 4; mt++) {
                    #pragma unroll
                    for (int nt = 0; nt < 4; nt++) {
                        const int np = nt >> 1, no = nt & 1;
                        MMA_16816_F16(acc[mt][nt][0], acc[mt][nt][1], acc[mt][nt][2], acc[mt][nt][3],
                                      a[mt][0], a[mt][1], a[mt][2], a[mt][3],
                                      b[np][no], b[np][2 + no]);
                    }
                }
            }
        }
        st = (st + 1 == NSTAGE) ? 0 : st + 1;
    }

    // epilogue: accum -> g_logits
    const int mrow = lid >> 2;
    const int mcol = (lid & 3) * 2;
    #pragma unroll
    for (int mt = 0; mt < 4; mt++) {
        #pragma unroll
        for (int nt = 0; nt < 4; nt++) {
            const int row = bm + wm + mt * 16 + mrow;
            const int col = bn + wn + nt * 8 + mcol;
            float2 v01 = make_float2(acc[mt][nt][0], acc[mt][nt][1]);
            float2 v23 = make_float2(acc[mt][nt][2], acc[mt][nt][3]);
            *(float2*)(g_logits + (size_t)row * K_DIM + col) = v01;
            *(float2*)(g_logits + (size_t)(row + 8) * K_DIM + col) = v23;
        }
    }
}

// ---------------- K2: column pass -------------------------------------------------
__global__ void __launch_bounds__(256) colpass_kernel() {
    const int k = blockIdx.x * 256 + threadIdx.x;
    const int bc = blockIdx.y;
    const int s = blockIdx.z;
    const float* __restrict__ base =
        g_logits + ((size_t)(s * B_DIM + bc * 1024)) * K_DIM + k;
    float m = -1e30f, sum = 0.f;
    for (int b0 = 0; b0 < 1024; b0 += 8) {
        float v[8];
        #pragma unroll
        for (int j = 0; j < 8; j++) v[j] = base[(size_t)(b0 + j) * K_DIM] * 20.0f;
        #pragma unroll
        for (int j = 0; j < 8; j++) {
            if (v[j] <= m) sum += fast_exp(v[j] - m);
            else { sum = fmaf(sum, fast_exp(m - v[j]), 1.0f); m = v[j]; }
        }
    }
    const int pidx = (bc * S_DIM + s) * K_DIM + k;
    g_part_m[pidx] = m;
    g_part_s[pidx] = sum;
}

__global__ void __launch_bounds__(256) combine1_kernel() {
    const int idx = blockIdx.x * 256 + threadIdx.x;
    const int s = idx >> 13, k = idx & (K_DIM - 1);
    float m = -1e30f;
    #pragma unroll
    for (int bc = 0; bc < 4; bc++)
        m = fmaxf(m, g_part_m[(bc * S_DIM + s) * K_DIM + k]);
    float A = 0.f;
    #pragma unroll
    for (int bc = 0; bc < 4; bc++) {
        const int pi = (bc * S_DIM + s) * K_DIM + k;
        A = fmaf(g_part_s[pi], fast_exp(g_part_m[pi] - m), A);
    }
    float A1 = 5.1847055285870724e21f * A;   // * exp(50)
    g_shift[idx] = m;
    g_c[idx] = 1.0f / (A1 + 1e-8f);
    g_A[idx] = 0.f;
}

__global__ void __launch_bounds__(256) update_c_kernel() {
    const int idx = blockIdx.x * 256 + threadIdx.x;
    float c = g_c[idx], A = g_A[idx];
    g_c[idx] = c / (c * A + 1e-8f);
    g_A[idx] = 0.f;
    if (idx == 0) g_loss = 0.f;
}

// ---------------- row passes (smem ebuf, 16 rows/CTA, high occupancy) -------------
template <int MODE>
__global__ void __launch_bounds__(256) rowpass_kernel(float* __restrict__ outp) {
    __shared__ float seb[32 * 256];
    __shared__ float sA[8], sB[8], sC[8];
    __shared__ float bcast[1];
    const int tid = threadIdx.x;
    const int warp = tid >> 5, lane = tid & 31;
    const int r0 = blockIdx.x * RPC;
    const int s = r0 >> 12;
    const float* __restrict__ shiftv = g_shift + s * K_DIM;
    const float* __restrict__ cv = g_c + s * K_DIM;

    float accR[32];
    if (MODE != 3) {
        #pragma unroll
        for (int j = 0; j < 32; j++) accR[j] = 0.f;
    }
    float lossAcc = 0.f;

    for (int rr = 0; rr < RPC; rr++) {
        const int row = r0 + rr;
        const float* __restrict__ lrow = g_logits + (size_t)row * K_DIM;
        float sumB = 0.f, sumV = 0.f;
        float lm = -1e30f, ls = 0.f;
        #pragma unroll
        for (int j = 0; j < 32; j++) {
            const int k = tid + (j << 8);
            float l = lrow[k];
            float e = fast_exp(fmaf(l, 20.0f, 50.0f - shiftv[k]));
            float t = e * cv[k];
            sumB += t;
            if (MODE == 3) {
                seb[(j << 8) + tid] = t;
                sumV = fmaf(t, l * 8.3333333333333339f, sumV);
            } else {
                seb[(j << 8) + tid] = e;
            }
            if (MODE == 1) {
                float pp = l * 8.3333333333333339f;
                if (pp <= lm) ls += fast_exp(pp - lm);
                else { ls = fmaf(ls, fast_exp(lm - pp), 1.0f); lm = pp; }
            }
        }
        #pragma unroll
        for (int o = 16; o > 0; o >>= 1) {
            sumB += __shfl_xor_sync(0xffffffffu, sumB, o);
            if (MODE == 3) sumV += __shfl_xor_sync(0xffffffffu, sumV, o);
            if (MODE == 1) {
                float m2 = __shfl_xor_sync(0xffffffffu, lm, o);
                float s2 = __shfl_xor_sync(0xffffffffu, ls, o);
                float mm = fmaxf(lm, m2);
                ls = ls * fast_exp(lm - mm) + s2 * fast_exp(m2 - mm);
                lm = mm;
            }
        }
        if (lane == 0) {
            sA[warp] = sumB;
            if (MODE == 3) sB[warp] = sumV;
            if (MODE == 1) { sB[warp] = lm; sC[warp] = ls; }
        }
        __syncthreads();
        if (tid == 0) {
            float Bt = 0.f, Vt = 0.f, Mt = -1e30f, St = 0.f;
            #pragma unroll
            for (int w = 0; w < 8; w++) {
                Bt += sA[w];
                if (MODE == 3) Vt += sB[w];
                if (MODE == 1) {
                    float m2 = sB[w], s2 = sC[w];
                    float mm = fmaxf(Mt, m2);
                    St = St * fast_exp(Mt - mm) + s2 * fast_exp(m2 - mm);
                    Mt = mm;
                }
            }
            float rnew;
            if (MODE == 1) {
                rnew = 1.0f / (Bt + 1e-8f);
                g_r[row] = rnew;
                g_lse[row] = Mt + logf(St);
            } else {
                float rold = g_r[row];
                rnew = rold / (rold * Bt + 1e-8f);
                if (MODE == 2) g_r[row] = rnew;
                if (MODE == 3) lossAcc = fmaf(rnew, g_lse[row] * Bt - Vt, lossAcc);
            }
            bcast[0] = rnew;
        }
        __syncthreads();
        const float rnew = bcast[0];
        if (MODE == 3) {
            float* orow = outp + (size_t)row * K_DIM;
            #pragma unroll
            for (int j = 0; j < 32; j++) orow[tid + (j << 8)] = seb[(j << 8) + tid] * rnew;
        } else {
            #pragma unroll
            for (int j = 0; j < 32; j++)
                accR[j] = fmaf(seb[(j << 8) + tid], rnew, accR[j]);
        }
        __syncthreads();
    }

    if (MODE != 3) {
        float* Ag = g_A + s * K_DIM;
        #pragma unroll
        for (int j = 0; j < 32; j++) atomicAdd(&Ag[tid + (j << 8)], accR[j]);
    } else {
        if (tid == 0) atomicAdd(&g_loss, lossAcc);
    }
}

__global__ void finalize_kernel(float* dst) {
    dst[0] = g_loss * (1.0f / 16384.0f);
}

// ---------------- launch ----------------------------------------------------------
extern "C" void kernel_launch(void* const* d_in, const int* in_sizes, int n_in,
                              void* d_out, int out_size) {
    const float* x = (const float*)d_in[0];
    const float* W = (const float*)d_in[1];
    if (n_in >= 2 && in_sizes[0] == K_DIM * D_DIM && in_sizes[1] == N_ROWS * D_DIM) {
        const float* t = x; x = W; W = t;
    }
    float* out = (float*)d_out;

    float* outp = out;
    if ((long long)out_size < TOT_ELEMS) {
        void* p = nullptr;
        cudaGetSymbolAddress(&p, g_logits);
        outp = (float*)p;
    }

    void *pA, *pB;
    cudaGetSymbolAddress(&pA, g_Acat);
    cudaGetSymbolAddress(&pB, g_Bcat);

    cudaFuncSetAttribute(gemm_hmma, cudaFuncAttributeMaxDynamicSharedMemorySize, GEMM_SMEM);

    norm_kernel<<<N_ROWS / 8, 256>>>(x);
    convA_kernel<<<(N_ROWS * 96) / 256, 256>>>(x);
    convB_kernel<<<(K_DIM * 96) / 256, 256>>>(W);

    gemm_hmma<<<dim3(K_DIM / BN, N_ROWS / BM), 256, GEMM_SMEM>>>(
        (const uint8_t*)pA, (const uint8_t*)pB);

    colpass_kernel<<<dim3(K_DIM / 256, 4, S_DIM), 256>>>();
    combine1_kernel<<<(S_DIM * K_DIM) / 256, 256>>>();

    rowpass_kernel<1><<<N_ROWS / RPC, 256>>>(nullptr);
    update_c_kernel<<<(S_DIM * K_DIM) / 256, 256>>>();
    rowpass_kernel<2><<<N_ROWS / RPC, 256>>>(nullptr);
    update_c_kernel<<<(S_DIM * K_DIM) / 256, 256>>>();
    rowpass_kernel<3><<<N_ROWS / RPC, 256>>>(outp);

    if ((long long)out_size > TOT_ELEMS) {
        finalize_kernel<<<1, 1>>>(out + TOT_ELEMS);
    } else if (out_size == 1) {
        finalize_kernel<<<1, 1>>>(out);
    }
}

// round 11
// speedup vs baseline: 1.3862x; 1.3862x over previous
#include <cuda_runtime.h>
#include <cuda_bf16.h>
#include <math.h>
#include <stdint.h>

#define S_DIM 4
#define B_DIM 4096
#define D_DIM 768
#define K_DIM 8192
#define N_ROWS 16384
#define RPC 16                  // rows per CTA in row passes
#define TOT_ELEMS 134217728LL   // N_ROWS * K_DIM

#define KTOT 2304               // 3 * D_DIM (concatenated split planes)

// ---------------- scratch (device globals; no allocation allowed) ----------------
__device__ float g_logits[(size_t)N_ROWS * K_DIM];   // 512 MB
__device__ float g_inv_norm[N_ROWS];
__device__ float g_shift[S_DIM * K_DIM];
__device__ float g_c[S_DIM * K_DIM];
__device__ float g_A[S_DIM * K_DIM];
__device__ float g_r[N_ROWS];
__device__ float g_lse[N_ROWS];
// per-mtile column partials written by the GEMM epilogue: [32 mtiles][S][K]
__device__ float g_part_m[32 * S_DIM * K_DIM];
__device__ float g_part_s[32 * S_DIM * K_DIM];
__device__ float g_loss;

// concatenated bf16 split planes:  A3 = [Ah | Ah | Am],  B3 = [Bh | Bm | Bh]
__device__ __nv_bfloat16 g_A3[(size_t)N_ROWS * KTOT];   // 75.5 MB
__device__ __nv_bfloat16 g_B3[(size_t)K_DIM * KTOT];    // 37.7 MB

// ---------------- helpers ---------------------------------------------------------
__device__ __forceinline__ uint32_t smem_u32(const void* p) {
    uint32_t a;
    asm("{ .reg .u64 t; cvta.to.shared.u64 t, %1; cvt.u32.u64 %0, t; }" : "=r"(a) : "l"(p));
    return a;
}

#define CP_ASYNC16(s, g) \
    asm volatile("cp.async.cg.shared.global [%0], [%1], 16;" :: "r"(s), "l"(g) : "memory")
#define CP_COMMIT() asm volatile("cp.async.commit_group;" ::: "memory")
#define CP_WAIT1()  asm volatile("cp.async.wait_group 1;" ::: "memory")

#define LDMATRIX_X4(r0, r1, r2, r3, addr) \
    asm volatile("ldmatrix.sync.aligned.m8n8.x4.shared.b16 {%0,%1,%2,%3}, [%4];" \
        : "=r"(r0), "=r"(r1), "=r"(r2), "=r"(r3) : "r"(addr))

#define MMA_16816(c0, c1, c2, c3, a0, a1, a2, a3, b0, b1) \
    asm volatile("mma.sync.aligned.m16n8k16.row.col.f32.bf16.bf16.f32 " \
        "{%0,%1,%2,%3}, {%4,%5,%6,%7}, {%8,%9}, {%0,%1,%2,%3};" \
        : "+f"(c0), "+f"(c1), "+f"(c2), "+f"(c3) \
        : "r"(a0), "r"(a1), "r"(a2), "r"(a3), "r"(b0), "r"(b1))

// ---------------- fast exp on the FMA pipe (rel err ~1e-7 for x <= 50) ----------
__device__ __forceinline__ float fast_exp(float x) {
    float t = x * 1.4426950408889634f;
    t = fmaxf(t, -127.0f);
    float n = rintf(t);
    float f = t - n;
    float p = 1.5403530393381609e-4f;
    p = fmaf(p, f, 1.3333558146428443e-3f);
    p = fmaf(p, f, 9.6181291076284772e-3f);
    p = fmaf(p, f, 5.5504108664821580e-2f);
    p = fmaf(p, f, 2.4022650695910072e-1f);
    p = fmaf(p, f, 6.9314718055994531e-1f);
    p = fmaf(p, f, 1.0f);
    return __int_as_float(((int)n + 127) << 23) * p;
}

// ---------------- K0: row norms ---------------------------------------------------
__global__ void __launch_bounds__(256) norm_kernel(const float* __restrict__ X) {
    int row = blockIdx.x * 8 + (threadIdx.x >> 5);
    int lane = threadIdx.x & 31;
    const float* xr = X + (size_t)row * D_DIM;
    float ss = 0.f;
    for (int i = lane; i < D_DIM; i += 32) { float v = xr[i]; ss = fmaf(v, v, ss); }
    #pragma unroll
    for (int o = 16; o > 0; o >>= 1) ss += __shfl_xor_sync(0xffffffffu, ss, o);
    if (lane == 0) g_inv_norm[row] = 1.0f / fmaxf(sqrtf(ss), 1e-7f);
}

// ---------------- split converters ------------------------------------------------
__global__ void __launch_bounds__(256) convA_kernel(const float* __restrict__ X) {
    size_t g = (size_t)blockIdx.x * 256 + threadIdx.x;   // pair index
    int row = (int)(g / (D_DIM / 2));
    int c2 = (int)(g % (D_DIM / 2)) * 2;
    float sc = g_inv_norm[row];
    float2 v = *(const float2*)(X + (size_t)row * D_DIM + c2);
    float a0 = v.x * sc, a1 = v.y * sc;
    __nv_bfloat16 h0 = __float2bfloat16(a0);
    __nv_bfloat16 h1 = __float2bfloat16(a1);
    __nv_bfloat16 m0 = __float2bfloat16(a0 - __bfloat162float(h0));
    __nv_bfloat16 m1 = __float2bfloat16(a1 - __bfloat162float(h1));
    __nv_bfloat16* rowp = g_A3 + (size_t)row * KTOT;
    *(__nv_bfloat162*)(rowp + c2)             = __nv_bfloat162(h0, h1);
    *(__nv_bfloat162*)(rowp + D_DIM + c2)     = __nv_bfloat162(h0, h1);
    *(__nv_bfloat162*)(rowp + 2 * D_DIM + c2) = __nv_bfloat162(m0, m1);
}

__global__ void __launch_bounds__(256) convB_kernel(const float* __restrict__ Wm) {
    size_t g = (size_t)blockIdx.x * 256 + threadIdx.x;
    int row = (int)(g / (D_DIM / 2));
    int c2 = (int)(g % (D_DIM / 2)) * 2;
    float2 v = *(const float2*)(Wm + (size_t)row * D_DIM + c2);
    __nv_bfloat16 h0 = __float2bfloat16(v.x);
    __nv_bfloat16 h1 = __float2bfloat16(v.y);
    __nv_bfloat16 m0 = __float2bfloat16(v.x - __bfloat162float(h0));
    __nv_bfloat16 m1 = __float2bfloat16(v.y - __bfloat162float(h1));
    __nv_bfloat16* rowp = g_B3 + (size_t)row * KTOT;
    *(__nv_bfloat162*)(rowp + c2)             = __nv_bfloat162(h0, h1);
    *(__nv_bfloat162*)(rowp + D_DIM + c2)     = __nv_bfloat162(m0, m1);
    *(__nv_bfloat162*)(rowp + 2 * D_DIM + c2) = __nv_bfloat162(h0, h1);
}

// ---------------- K1: HMMA GEMM (bf16x2 split, K=2304) + fused column stats ------
// 128x128 CTA, 8 warps of 64x32, 2 CTA/SM, BKK=64 (R8 champion shape).
// Epilogue additionally computes per-column online (max, sum-exp) over the CTA's
// 128 rows of v = 20*logit and writes one partial per column (no atomics).
#define BM 128
#define BN 128
#define BKK 64
#define NIT (KTOT / BKK)            // 36
#define RSTR 144                    // padded row: 128B + 16B ((9r+c)%8 permutation)
#define STAGE_HALF (128 * RSTR)     // 18432 B per matrix per stage
#define STAGE_BYTES (2 * STAGE_HALF)   // 36864
#define NSTAGE 3
#define GEMM_SMEM (NSTAGE * STAGE_BYTES)   // 110592 (2 CTA/SM)

__global__ void __launch_bounds__(256, 2) gemm_hmma(const __nv_bfloat16* __restrict__ A3,
                                                    const __nv_bfloat16* __restrict__ B3) {
    extern __shared__ char smem[];
    const uint32_t sbase = smem_u32(smem);
    const int tid = threadIdx.x;
    const int wid = tid >> 5, lid = tid & 31;
    const int bm = blockIdx.y * BM;
    const int bn = blockIdx.x * BN;
    const int wm = (wid & 1) * 64;      // 2 warps in m
    const int wn = (wid >> 1) * 32;     // 4 warps in n

    const __nv_bfloat16* gA[4];
    const __nv_bfloat16* gB[4];
    uint32_t so[4];
    #pragma unroll
    for (int i = 0; i < 4; i++) {
        const int ch = tid + i * 256;
        const int r = ch >> 3, c = ch & 7;
        gA[i] = A3 + (size_t)(bm + r) * KTOT + c * 8;
        gB[i] = B3 + (size_t)(bn + r) * KTOT + c * 8;
        so[i] = r * RSTR + c * 16;
    }

    const int lrow = (lid & 7) + ((lid >> 3) & 1) * 8;
    const int lkb = ((lid >> 4) & 1) * 16;
    const uint32_t aoff = (uint32_t)(wm + lrow) * RSTR + lkb;
    const uint32_t boff = (uint32_t)(wn + lrow) * RSTR + lkb;

    float acc[4][4][4];
    #pragma unroll
    for (int i = 0; i < 4; i++)
        #pragma unroll
        for (int j = 0; j < 4; j++)
            #pragma unroll
            for (int q = 0; q < 4; q++) acc[i][j][q] = 0.f;

    #pragma unroll
    for (int st = 0; st < 2; st++) {
        const int k0 = st * BKK;
        const uint32_t sa = sbase + st * STAGE_BYTES;
        const uint32_t sb = sa + STAGE_HALF;
        #pragma unroll
        for (int i = 0; i < 4; i++) {
            CP_ASYNC16(sa + so[i], gA[i] + k0);
            CP_ASYNC16(sb + so[i], gB[i] + k0);
        }
        CP_COMMIT();
    }

    int st = 0;
    for (int it = 0; it < NIT; it++) {
        CP_WAIT1();
        __syncthreads();

        if (it + 2 < NIT) {
            const int ps = (st + 2 >= NSTAGE) ? st + 2 - NSTAGE : st + 2;
            const int k0 = (it + 2) * BKK;
            const uint32_t sa = sbase + ps * STAGE_BYTES;
            const uint32_t sb = sa + STAGE_HALF;
            #pragma unroll
            for (int i = 0; i < 4; i++) {
                CP_ASYNC16(sa + so[i], gA[i] + k0);
                CP_ASYNC16(sb + so[i], gB[i] + k0);
            }
        }
        CP_COMMIT();

        const uint32_t sa = sbase + st * STAGE_BYTES;
        const uint32_t sb = sa + STAGE_HALF;
        #pragma unroll
        for (int ks = 0; ks < 4; ks++) {
            uint32_t a[4][4];
            #pragma unroll
            for (int mt = 0; mt < 4; mt++) {
                uint32_t ad = sa + aoff + mt * (16 * RSTR) + ks * 32;
                LDMATRIX_X4(a[mt][0], a[mt][1], a[mt][2], a[mt][3], ad);
            }
            uint32_t b[2][4];
            #pragma unroll
            for (int np = 0; np < 2; np++) {
                uint32_t bd = sb + boff + np * (16 * RSTR) + ks * 32;
                LDMATRIX_X4(b[np][0], b[np][1], b[np][2], b[np][3], bd);
            }
            #pragma unroll
            for (int mt = 0; mt < 4; mt++) {
                #pragma unroll
                for (int nt = 0; nt < 4; nt++) {
                    const int np = nt >> 1, no = nt & 1;
                    MMA_16816(acc[mt][nt][0], acc[mt][nt][1], acc[mt][nt][2], acc[mt][nt][3],
                              a[mt][0], a[mt][1], a[mt][2], a[mt][3],
                              b[np][no], b[np][2 + no]);
                }
            }
        }
        st = (st + 1 == NSTAGE) ? 0 : st + 1;
    }

    // ---- epilogue part 1: per-thread column stats (8 columns x 8 rows each) ----
    // thread's column i = nt*2+o  ->  CTA column  wn + nt*8 + (lid&3)*2 + o
    float cm[8], cs[8];
    #pragma unroll
    for (int nt = 0; nt < 4; nt++) {
        #pragma unroll
        for (int o = 0; o < 2; o++) {
            float mx = -1e30f;
            #pragma unroll
            for (int mt = 0; mt < 4; mt++) {
                mx = fmaxf(mx, acc[mt][nt][o]);
                mx = fmaxf(mx, acc[mt][nt][2 + o]);
            }
            mx *= 20.0f;
            float sm = 0.f;
            #pragma unroll
            for (int mt = 0; mt < 4; mt++) {
                sm += fast_exp(fmaf(acc[mt][nt][o], 20.0f, -mx));
                sm += fast_exp(fmaf(acc[mt][nt][2 + o], 20.0f, -mx));
            }
            cm[nt * 2 + o] = mx;
            cs[nt * 2 + o] = sm;
        }
    }
    // reduce across the 8 row-lane-groups (lid>>2) of the warp
    #pragma unroll
    for (int off = 4; off <= 16; off <<= 1) {
        #pragma unroll
        for (int i = 0; i < 8; i++) {
            float m2 = __shfl_xor_sync(0xffffffffu, cm[i], off);
            float s2 = __shfl_xor_sync(0xffffffffu, cs[i], off);
            float nm = fmaxf(cm[i], m2);
            cs[i] = cs[i] * fast_exp(cm[i] - nm) + s2 * fast_exp(m2 - nm);
            cm[i] = nm;
        }
    }

    // ---- epilogue part 2: store logits ----
    const int mrow = lid >> 2;
    const int mcol = (lid & 3) * 2;
    #pragma unroll
    for (int mt = 0; mt < 4; mt++) {
        #pragma unroll
        for (int nt = 0; nt < 4; nt++) {
            const int row = bm + wm + mt * 16 + mrow;
            const int col = bn + wn + nt * 8 + mcol;
            float2 v01 = make_float2(acc[mt][nt][0], acc[mt][nt][1]);
            float2 v23 = make_float2(acc[mt][nt][2], acc[mt][nt][3]);
            *(float2*)(g_logits + (size_t)row * K_DIM + col) = v01;
            *(float2*)(g_logits + (size_t)(row + 8) * K_DIM + col) = v23;
        }
    }

    // ---- epilogue part 3: combine the two m-warps, write per-CTA partial ----
    float* sbuf = (float*)smem;   // reuse pipeline smem: [128 cols][2]
    __syncthreads();
    if ((wid & 1) == 0 && lid < 4) {
        #pragma unroll
        for (int i = 0; i < 8; i++) {
            int c = (wid >> 1) * 32 + (i >> 1) * 8 + lid * 2 + (i & 1);
            sbuf[c * 2] = cm[i];
            sbuf[c * 2 + 1] = cs[i];
        }
    }
    __syncthreads();
    if ((wid & 1) == 1 && lid < 4) {
        const int mt32 = (bm & 4095) >> 7;   // m-tile index within its s-slice
        const int sidx = bm >> 12;
        #pragma unroll
        for (int i = 0; i < 8; i++) {
            int c = (wid >> 1) * 32 + (i >> 1) * 8 + lid * 2 + (i & 1);
            float m2 = sbuf[c * 2], s2 = sbuf[c * 2 + 1];
            float nm = fmaxf(cm[i], m2);
            float ns = cs[i] * fast_exp(cm[i] - nm) + s2 * fast_exp(m2 - nm);
            int gidx = (mt32 * S_DIM + sidx) * K_DIM + bn + c;
            g_part_m[gidx] = nm;
            g_part_s[gidx] = ns;
        }
    }
}

// ---------------- K2: combine per-mtile partials -> shift, c1; zero A ------------
__global__ void __launch_bounds__(256) combine1_kernel() {
    const int idx = blockIdx.x * 256 + threadIdx.x;     // s*K + k
    const int s = idx >> 13, k = idx & (K_DIM - 1);
    float m = -1e30f;
    #pragma unroll
    for (int i = 0; i < 32; i++)
        m = fmaxf(m, g_part_m[(i * S_DIM + s) * K_DIM + k]);
    float A = 0.f;
    #pragma unroll
    for (int i = 0; i < 32; i++) {
        const int pi = (i * S_DIM + s) * K_DIM + k;
        A = fmaf(g_part_s[pi], fast_exp(g_part_m[pi] - m), A);
    }
    float A1 = 5.1847055285870724e21f * A;   // * exp(50)
    g_shift[idx] = m;
    g_c[idx] = 1.0f / (A1 + 1e-8f);
    g_A[idx] = 0.f;
}

__global__ void __launch_bounds__(256) update_c_kernel() {
    const int idx = blockIdx.x * 256 + threadIdx.x;
    float c = g_c[idx], A = g_A[idx];
    g_c[idx] = c / (c * A + 1e-8f);
    g_A[idx] = 0.f;
    if (idx == 0) g_loss = 0.f;
}

// ---------------- row passes (smem ebuf, 16 rows/CTA, high occupancy) -------------
template <int MODE>
__global__ void __launch_bounds__(256) rowpass_kernel(float* __restrict__ outp) {
    __shared__ float seb[32 * 256];
    __shared__ float sA[8], sB[8], sC[8];
    __shared__ float bcast[1];
    const int tid = threadIdx.x;
    const int warp = tid >> 5, lane = tid & 31;
    const int r0 = blockIdx.x * RPC;
    const int s = r0 >> 12;
    const float* __restrict__ shiftv = g_shift + s * K_DIM;
    const float* __restrict__ cv = g_c + s * K_DIM;

    float accR[32];
    if (MODE != 3) {
        #pragma unroll
        for (int j = 0; j < 32; j++) accR[j] = 0.f;
    }
    float lossAcc = 0.f;

    for (int rr = 0; rr < RPC; rr++) {
        const int row = r0 + rr;
        const float* __restrict__ lrow = g_logits + (size_t)row * K_DIM;
        float sumB = 0.f, sumV = 0.f;
        float lm = -1e30f, ls = 0.f;
        #pragma unroll
        for (int j = 0; j < 32; j++) {
            const int k = tid + (j << 8);
            float l = lrow[k];
            float e = fast_exp(fmaf(l, 20.0f, 50.0f - shiftv[k]));
            float t = e * cv[k];
            sumB += t;
            if (MODE == 3) {
                seb[(j << 8) + tid] = t;
                sumV = fmaf(t, l * 8.3333333333333339f, sumV);
            } else {
                seb[(j << 8) + tid] = e;
            }
            if (MODE == 1) {
                float pp = l * 8.3333333333333339f;
                if (pp <= lm) ls += fast_exp(pp - lm);
                else { ls = fmaf(ls, fast_exp(lm - pp), 1.0f); lm = pp; }
            }
        }
        #pragma unroll
        for (int o = 16; o > 0; o >>= 1) {
            sumB += __shfl_xor_sync(0xffffffffu, sumB, o);
            if (MODE == 3) sumV += __shfl_xor_sync(0xffffffffu, sumV, o);
            if (MODE == 1) {
                float m2 = __shfl_xor_sync(0xffffffffu, lm, o);
                float s2 = __shfl_xor_sync(0xffffffffu, ls, o);
                float mm = fmaxf(lm, m2);
                ls = ls * fast_exp(lm - mm) + s2 * fast_exp(m2 - mm);
                lm = mm;
            }
        }
        if (lane == 0) {
            sA[warp] = sumB;
            if (MODE == 3) sB[warp] = sumV;
            if (MODE == 1) { sB[warp] = lm; sC[warp] = ls; }
        }
        __syncthreads();
        if (tid == 0) {
            float Bt = 0.f, Vt = 0.f, Mt = -1e30f, St = 0.f;
            #pragma unroll
            for (int w = 0; w < 8; w++) {
                Bt += sA[w];
                if (MODE == 3) Vt += sB[w];
                if (MODE == 1) {
                    float m2 = sB[w], s2 = sC[w];
                    float mm = fmaxf(Mt, m2);
                    St = St * fast_exp(Mt - mm) + s2 * fast_exp(m2 - mm);
                    Mt = mm;
                }
            }
            float rnew;
            if (MODE == 1) {
                rnew = 1.0f / (Bt + 1e-8f);
                g_r[row] = rnew;
                g_lse[row] = Mt + logf(St);
            } else {
                float rold = g_r[row];
                rnew = rold / (rold * Bt + 1e-8f);
                if (MODE == 2) g_r[row] = rnew;
                if (MODE == 3) lossAcc = fmaf(rnew, g_lse[row] * Bt - Vt, lossAcc);
            }
            bcast[0] = rnew;
        }
        __syncthreads();
        const float rnew = bcast[0];
        if (MODE == 3) {
            float* orow = outp + (size_t)row * K_DIM;
            #pragma unroll
            for (int j = 0; j < 32; j++) orow[tid + (j << 8)] = seb[(j << 8) + tid] * rnew;
        } else {
            #pragma unroll
            for (int j = 0; j < 32; j++)
                accR[j] = fmaf(seb[(j << 8) + tid], rnew, accR[j]);
        }
        __syncthreads();
    }

    if (MODE != 3) {
        float* Ag = g_A + s * K_DIM;
        #pragma unroll
        for (int j = 0; j < 32; j++) atomicAdd(&Ag[tid + (j << 8)], accR[j]);
    } else {
        if (tid == 0) atomicAdd(&g_loss, lossAcc);
    }
}

__global__ void finalize_kernel(float* dst) {
    dst[0] = g_loss * (1.0f / 16384.0f);
}

// ---------------- launch ----------------------------------------------------------
extern "C" void kernel_launch(void* const* d_in, const int* in_sizes, int n_in,
                              void* d_out, int out_size) {
    const float* x = (const float*)d_in[0];
    const float* W = (const float*)d_in[1];
    if (n_in >= 2 && in_sizes[0] == K_DIM * D_DIM && in_sizes[1] == N_ROWS * D_DIM) {
        const float* t = x; x = W; W = t;
    }
    float* out = (float*)d_out;

    float* outp = out;
    if ((long long)out_size < TOT_ELEMS) {
        void* p = nullptr;
        cudaGetSymbolAddress(&p, g_logits);
        outp = (float*)p;
    }

    void *pA3, *pB3;
    cudaGetSymbolAddress(&pA3, g_A3);
    cudaGetSymbolAddress(&pB3, g_B3);

    cudaFuncSetAttribute(gemm_hmma, cudaFuncAttributeMaxDynamicSharedMemorySize, GEMM_SMEM);

    norm_kernel<<<N_ROWS / 8, 256>>>(x);
    convA_kernel<<<(N_ROWS * (D_DIM / 2)) / 256, 256>>>(x);
    convB_kernel<<<(K_DIM * (D_DIM / 2)) / 256, 256>>>(W);

    gemm_hmma<<<dim3(K_DIM / BN, N_ROWS / BM), 256, GEMM_SMEM>>>(
        (const __nv_bfloat16*)pA3, (const __nv_bfloat16*)pB3);

    combine1_kernel<<<(S_DIM * K_DIM) / 256, 256>>>();

    rowpass_kernel<1><<<N_ROWS / RPC, 256>>>(nullptr);
    update_c_kernel<<<(S_DIM * K_DIM) / 256, 256>>>();
    rowpass_kernel<2><<<N_ROWS / RPC, 256>>>(nullptr);
    update_c_kernel<<<(S_DIM * K_DIM) / 256, 256>>>();
    rowpass_kernel<3><<<N_ROWS / RPC, 256>>>(outp);

    if ((long long)out_size > TOT_ELEMS) {
        finalize_kernel<<<1, 1>>>(out + TOT_ELEMS);
    } else if (out_size == 1) {
        finalize_kernel<<<1, 1>>>(out);
    }
}